// round 8
// baseline (speedup 1.0000x reference)
#include <cuda_runtime.h>
#include <math_constants.h>

// Statically-initialized accumulators; the last block resets them after use,
// so every graph replay sees zeros. No cudaMalloc, no extra launches.
__device__ double g_eme_sum = 0.0;
__device__ unsigned int g_eme_count = 0u;

// Warp-cooperative: each warp owns 32 consecutive 8x8 windows (one 256-float
// contiguous span per image row). Every LDG.128 instruction covers a
// contiguous 512B (4 full 128B lines, nL=4) instead of 8 half-used lines.
// Lane l accumulates window (l>>1) from load A and window 16+(l>>1) from
// load B; one shfl_xor(1) merge completes each window's min/max.
// Input: (32,3,1024,1024) fp32 = 96 images of 1024x1024; 16384 windows/image.
// Grid: 6144 blocks x 256 threads; warp W handles windows [W*32, W*32+32).
__global__ __launch_bounds__(256, 3) void eme_fused_kernel(
    const float* __restrict__ y, float* __restrict__ out)
{
    const int lane = threadIdx.x & 31;
    const int wid  = threadIdx.x >> 5;

    const int wbase = (blockIdx.x * 8 + wid) * 32;   // first window of this warp
    const int img = wbase >> 14;            // 16384 windows per image
    const int rem = wbase & 16383;
    const int wy  = rem >> 7;               // window row 0..127
    const int wx0 = rem & 127;              // first window col (multiple of 32)

    // Warp's span per image row: 32 windows * 8 floats = 256 floats = 1024 B.
    const float4* __restrict__ p = reinterpret_cast<const float4*>(
        y + (size_t)img * 1048576u + (size_t)wy * 8192u + (size_t)wx0 * 8u);
    // image row stride = 1024 floats = 256 float4

    // Front-batch all 16 loads (8 rows x {A,B}).
    float4 va[8], vb[8];
    #pragma unroll
    for (int r = 0; r < 8; r++) {
        va[r] = __ldcs(&p[r * 256 + lane]);        // bytes [0,512) of the span
        vb[r] = __ldcs(&p[r * 256 + 32 + lane]);   // bytes [512,1024)
    }

    float mxA = -CUDART_INF_F, mnA = CUDART_INF_F;
    float mxB = -CUDART_INF_F, mnB = CUDART_INF_F;
    #pragma unroll
    for (int r = 0; r < 8; r++) {
        mxA = fmaxf(mxA, fmaxf(fmaxf(va[r].x, va[r].y), fmaxf(va[r].z, va[r].w)));
        mnA = fminf(mnA, fminf(fminf(va[r].x, va[r].y), fminf(va[r].z, va[r].w)));
        mxB = fmaxf(mxB, fmaxf(fmaxf(vb[r].x, vb[r].y), fmaxf(vb[r].z, vb[r].w)));
        mnB = fminf(mnB, fminf(fminf(vb[r].x, vb[r].y), fminf(vb[r].z, vb[r].w)));
    }

    // Merge lane pairs: lanes 2k and 2k+1 each hold half of window k (A) and
    // window 16+k (B). After this, both lanes of a pair hold the full stats.
    mxA = fmaxf(mxA, __shfl_xor_sync(0xffffffffu, mxA, 1));
    mnA = fminf(mnA, __shfl_xor_sync(0xffffffffu, mnA, 1));
    mxB = fmaxf(mxB, __shfl_xor_sync(0xffffffffu, mxB, 1));
    mnB = fminf(mnB, __shfl_xor_sync(0xffffffffu, mnB, 1));

    // Even lanes evaluate both of their pair's windows; odd lanes contribute 0.
    float val = 0.0f;
    if ((lane & 1) == 0) {
        if (mxA != mnA) val += 20.0f * logf(mxA / (mnA + 1e-4f));
        if (mxB != mnB) val += 20.0f * logf(mxB / (mnB + 1e-4f));
    }

    // Intra-warp reduction.
    #pragma unroll
    for (int o = 16; o > 0; o >>= 1)
        val += __shfl_xor_sync(0xffffffffu, val, o);

    __shared__ float warp_sums[8];
    if (lane == 0) warp_sums[wid] = val;
    __syncthreads();

    if (wid == 0) {
        float vv = (lane < 8) ? warp_sums[lane] : 0.0f;
        #pragma unroll
        for (int o = 4; o > 0; o >>= 1)
            vv += __shfl_xor_sync(0xffffffffu, vv, o);

        if (lane == 0) {
            atomicAdd(&g_eme_sum, (double)vv);
            __threadfence();
            unsigned int done = atomicAdd(&g_eme_count, 1u);
            if (done == gridDim.x - 1u) {
                // All partials visible (each block fenced before incrementing).
                double s = g_eme_sum;
                // result = sum / (B * row * col / (w*w)) = sum / 524288
                out[0] = (float)(s * (1.0 / 524288.0));
                // Reset for the next graph replay.
                g_eme_sum = 0.0;
                g_eme_count = 0u;
            }
        }
    }
}

extern "C" void kernel_launch(void* const* d_in, const int* in_sizes, int n_in,
                              void* d_out, int out_size)
{
    const float* y = (const float*)d_in[0];
    float* out = (float*)d_out;

    const int n_windows = 32 * 3 * 128 * 128;  // 1,572,864
    const int threads = 256;
    const int blocks = n_windows / (threads / 32) / 32;  // 6144, exact

    eme_fused_kernel<<<blocks, threads>>>(y, out);
}

// round 9
// speedup vs baseline: 1.0010x; 1.0010x over previous
#include <cuda_runtime.h>
#include <math_constants.h>

// Statically-initialized accumulators; the last block resets them after use,
// so every graph replay sees zeros. No cudaMalloc, no extra launches.
__device__ double g_eme_sum = 0.0;
__device__ unsigned int g_eme_count = 0u;

// One thread per 8x8 window. Input logical shape (32,3,1024,1024) fp32,
// treated as 96 images of 1024x1024. Windows per image: 128x128.
// Grid: 6144 blocks x 256 threads = 1,572,864 windows exactly.
// min-blocks 3 -> 85-reg budget: front-batch ALL 16 LDG.128 of the window
// (64 data regs) to maximize per-warp memory-level parallelism (MLP_p1 = 16).
// Session evidence: this config is pinned at the chip's streaming-read
// ceiling (~6.4 TB/s); occupancy 29%-85% and layout variants all measure
// within 1% of this kernel.
__global__ __launch_bounds__(256, 3) void eme_fused_kernel(
    const float* __restrict__ y, float* __restrict__ out)
{
    const int w = blockIdx.x * 256 + threadIdx.x;

    const int img = w >> 14;          // 16384 windows per image
    const int rem = w & 16383;
    const int wy  = rem >> 7;         // window row 0..127
    const int wx  = rem & 127;        // window col 0..127

    const float4* __restrict__ p = reinterpret_cast<const float4*>(
        y + (size_t)img * 1048576u + (size_t)wy * 8192u + (size_t)wx * 8u);
    // image row stride = 1024 floats = 256 float4

    // Load the whole 8x8 window: 16 independent LDG.128 back-to-back.
    float4 v[16];
    #pragma unroll
    for (int r = 0; r < 8; r++) {
        v[2 * r]     = __ldcs(&p[r * 256]);
        v[2 * r + 1] = __ldcs(&p[r * 256 + 1]);
    }

    float mx = -CUDART_INF_F;
    float mn =  CUDART_INF_F;
    #pragma unroll
    for (int i = 0; i < 16; i++) {
        mx = fmaxf(mx, fmaxf(fmaxf(v[i].x, v[i].y), fmaxf(v[i].z, v[i].w)));
        mn = fminf(mn, fminf(fminf(v[i].x, v[i].y), fminf(v[i].z, v[i].w)));
    }

    float val = 0.0f;
    if (mx != mn) {
        val = 20.0f * logf(mx / (mn + 1e-4f));
    }

    // Intra-warp reduction.
    #pragma unroll
    for (int o = 16; o > 0; o >>= 1)
        val += __shfl_xor_sync(0xffffffffu, val, o);

    __shared__ float warp_sums[8];
    const int lane = threadIdx.x & 31;
    const int wid  = threadIdx.x >> 5;
    if (lane == 0) warp_sums[wid] = val;
    __syncthreads();

    if (wid == 0) {
        float vv = (lane < 8) ? warp_sums[lane] : 0.0f;
        #pragma unroll
        for (int o = 4; o > 0; o >>= 1)
            vv += __shfl_xor_sync(0xffffffffu, vv, o);

        if (lane == 0) {
            atomicAdd(&g_eme_sum, (double)vv);
            __threadfence();
            unsigned int done = atomicAdd(&g_eme_count, 1u);
            if (done == gridDim.x - 1u) {
                // All partials visible (each block fenced before incrementing).
                double s = g_eme_sum;
                // result = sum / (B * row * col / (w*w)) = sum / 524288
                out[0] = (float)(s * (1.0 / 524288.0));
                // Reset for the next graph replay.
                g_eme_sum = 0.0;
                g_eme_count = 0u;
            }
        }
    }
}

extern "C" void kernel_launch(void* const* d_in, const int* in_sizes, int n_in,
                              void* d_out, int out_size)
{
    const float* y = (const float*)d_in[0];
    float* out = (float*)d_out;

    const int n_windows = 32 * 3 * 128 * 128;  // 1,572,864
    const int threads = 256;
    const int blocks = n_windows / threads;    // 6144, exact

    eme_fused_kernel<<<blocks, threads>>>(y, out);
}